// round 8
// baseline (speedup 1.0000x reference)
#include <cuda_runtime.h>
#include <cuda_bf16.h>
#include <math.h>

#define BATCH 16384
#define FF    39
#define DD    16
#define DHD   32
#define VOCAB 10000
#define WARPS 14
#define NCTA  ((BATCH + WARPS - 1) / WARPS)   // 1171

// per-warp shared layout (float indices)
// e:      [0,1248)                     fp32 e / R / h
// kT:     [1248,2608) 40 rows x 34     fp32 K, ROW-REORDERED:
//           phys 0..7  = g 32..39 (g39=zeros)  -> PERSISTS through phase B
//           phys 8..39 = g 0..31                -> transient (klo reg-load),
//                                                  then aliased by qbh+sr
// qbh:    [1520,2300) bf16[39][40]     Q rows (bf16, pre-scaled by log2e)
// sr0/1:  [2300,2380)
// vstage: [2608,3952) 32 x 42          fp32 V staging (transient)
// mA/mB:  [1520,1648)/[1648,1712)      MLP hidden (over dead qbh)
#define KT_OFF   1248
#define KT_PITCH 34
#define QBH_OFF  1520
#define S_OFF    2300
#define VS_OFF   2608
#define VB_PITCH 42
#define MA_OFF   1520
#define MB_OFF   1648
#define PW       3952
#define WBUF     2048          // CTA w1 chunk: 1024 ull = 16 k-rows x 128 (8KB)

#define LOG2E 1.4426950408889634f

typedef unsigned long long ull;

__device__ __forceinline__ ull ffma2(ull a, ull b, ull c) {
  ull d; asm("fma.rn.f32x2 %0, %1, %2, %3;" : "=l"(d) : "l"(a), "l"(b), "l"(c));
  return d;
}
__device__ __forceinline__ ull fadd2(ull a, ull b) {
  ull d; asm("add.rn.f32x2 %0, %1, %2;" : "=l"(d) : "l"(a), "l"(b));
  return d;
}
__device__ __forceinline__ ull pack2(float lo, float hi) {
  ull v; unsigned int l = __float_as_uint(lo), h = __float_as_uint(hi);
  asm("mov.b64 %0, {%1, %2};" : "=l"(v) : "r"(l), "r"(h));
  return v;
}
__device__ __forceinline__ float hsum2(ull v) {
  unsigned int l, h;
  asm("mov.b64 {%0, %1}, %2;" : "=r"(l), "=r"(h) : "l"(v));
  return __uint_as_float(l) + __uint_as_float(h);
}
__device__ __forceinline__ float frcp(float x) {
  float r; asm("rcp.approx.f32 %0, %1;" : "=f"(r) : "f"(x));
  return r;
}
__device__ __forceinline__ float fex2(float x) {
  float r; asm("ex2.approx.f32 %0, %1;" : "=f"(r) : "f"(x));
  return r;
}
// bf16x2 word -> packed fp32 pair (lo=even elem, hi=odd elem)
__device__ __forceinline__ ull bf2pair(unsigned int w) {
  return pack2(__uint_as_float(w << 16), __uint_as_float(w & 0xffff0000u));
}
__device__ __forceinline__ void cfence() { asm volatile("" ::: "memory"); }

struct Params {
  const int* x; const float* emb;
  const float* wq0; const float* wk0; const float* wv0; const float* wr0;
  const float* wq1; const float* wk1; const float* wv1; const float* wr1;
  const float* wq2; const float* wk2; const float* wv2; const float* wr2;
  const float* w1; const float* b1; const float* w2; const float* b2;
  const float* w3; const float* b3; const float* w4; const float* b4;
  float* out;
};

template<int DIN>
__device__ __forceinline__ void attn_layer(
    float* wp,
    const float* __restrict__ wq, const float* __restrict__ wk,
    const float* __restrict__ wv, const float* __restrict__ wr, int lane)
{
  float* eB  = wp;
  float* kT  = wp + KT_OFF;
  __nv_bfloat16* qbh = (__nv_bfloat16*)(wp + QBH_OFF);
  float* vB2 = wp + VS_OFF;
  float* sr0 = wp + S_OFF;
  float* sr1 = wp + S_OFF + 40;
  constexpr int NP = DIN / 2;

  // ---- Pass 1: K -> kT (row-reordered), V -> vstage (transposed) ----
  {
    ull wkp[NP], wvp[NP];
    #pragma unroll
    for (int dp = 0; dp < NP; dp++) {
      wkp[dp] = pack2(wk[(2*dp)*DHD + lane], wk[(2*dp+1)*DHD + lane]);
      wvp[dp] = pack2(wv[(2*dp)*DHD + lane], wv[(2*dp+1)*DHD + lane]);
    }
    #pragma unroll 2
    for (int g = 0; g < FF; g++) {
      const ulonglong2* er = (const ulonglong2*)(eB + g*DHD);
      ull ka = 0ull, kb = 0ull, va = 0ull, vb = 0ull;
      #pragma unroll
      for (int q8 = 0; q8 < NP/2; q8++) {
        ulonglong2 ev = er[q8];
        ka = ffma2(ev.x, wkp[2*q8],   ka);  va = ffma2(ev.x, wvp[2*q8],   va);
        kb = ffma2(ev.y, wkp[2*q8+1], kb);  vb = ffma2(ev.y, wvp[2*q8+1], vb);
      }
      int pg = (g < 32) ? (g + 8) : (g - 32);   // row reorder
      kT[pg*KT_PITCH + lane]  = hsum2(fadd2(ka, kb));
      vB2[lane*VB_PITCH + g]  = hsum2(fadd2(va, vb));
    }
    vB2[lane*VB_PITCH + 39] = 0.f;
  }
  cfence();

  // ---- one-time register loads: K rows 0..31 (phys 8..39) and V column ----
  ull klo[16], vp[20];
  {
    #pragma unroll
    for (int dp = 0; dp < 16; dp++)
      klo[dp] = *(const ull*)&kT[(lane + 8)*KT_PITCH + 2*dp];
    #pragma unroll
    for (int gp = 0; gp < 20; gp++)
      vp[gp] = *(const ull*)&vB2[lane*VB_PITCH + 2*gp];
  }
  cfence();

  // ---- Pass 2: Q (bf16, pre-scaled log2e) -> qbh, R -> eB in place ----
  // NOTE: qbh aliases kT phys rows 8+ (already consumed into klo).
  {
    ull wqp[NP], wrp[NP];
    #pragma unroll
    for (int dp = 0; dp < NP; dp++) {
      wqp[dp] = pack2(wq[(2*dp)*DHD + lane] * LOG2E, wq[(2*dp+1)*DHD + lane] * LOG2E);
      wrp[dp] = pack2(wr[(2*dp)*DHD + lane], wr[(2*dp+1)*DHD + lane]);
    }
    #pragma unroll 2
    for (int g = 0; g < FF; g++) {
      const ulonglong2* er = (const ulonglong2*)(eB + g*DHD);
      ull qa = 0ull, qb = 0ull, ra = 0ull, rb = 0ull;
      #pragma unroll
      for (int q8 = 0; q8 < NP/2; q8++) {
        ulonglong2 ev = er[q8];
        qa = ffma2(ev.x, wqp[2*q8],   qa);  ra = ffma2(ev.x, wrp[2*q8],   ra);
        qb = ffma2(ev.y, wqp[2*q8+1], qb);  rb = ffma2(ev.y, wrp[2*q8+1], rb);
      }
      qbh[g*40 + lane] = __float2bfloat16(hsum2(fadd2(qa, qb)));
      eB[g*DHD + lane] = hsum2(fadd2(ra, rb));   // R over dead e
    }
  }
  cfence();

  // re-zero sr[39] (pass1 wrote kT over this region)
  if (lane == 0) { sr0[39] = 0.f; sr1[39] = 0.f; }
  cfence();

  const bool has2  = (lane < 7);
  const int  khrow = has2 ? lane : 7;   // phys rows 0..6 = K rows 32..38; row 7 zeros

  // ---- Phase B: scores (q from bf16), deferred-norm softmax, AV ----
  #pragma unroll 2
  for (int f = 0; f < FF; f++) {
    float* srf = (f & 1) ? sr1 : sr0;
    // load q row f (32 bf16 = 64B) and unpack to fp32 pairs
    const uint4* qr = (const uint4*)(qbh + f*40);
    uint4 w0 = qr[0], w1w = qr[1], w2w = qr[2], w3w = qr[3];
    ull qp[16];
    qp[0]=bf2pair(w0.x);  qp[1]=bf2pair(w0.y);  qp[2]=bf2pair(w0.z);  qp[3]=bf2pair(w0.w);
    qp[4]=bf2pair(w1w.x); qp[5]=bf2pair(w1w.y); qp[6]=bf2pair(w1w.z); qp[7]=bf2pair(w1w.w);
    qp[8]=bf2pair(w2w.x); qp[9]=bf2pair(w2w.y); qp[10]=bf2pair(w2w.z); qp[11]=bf2pair(w2w.w);
    qp[12]=bf2pair(w3w.x); qp[13]=bf2pair(w3w.y); qp[14]=bf2pair(w3w.z); qp[15]=bf2pair(w3w.w);

    const ull* kh = (const ull*)(kT + khrow*KT_PITCH);
    ull s1a = 0ull, s1b = 0ull, s2a = 0ull, s2b = 0ull;
    #pragma unroll
    for (int q8 = 0; q8 < 8; q8++) {
      s1a = ffma2(qp[2*q8],   klo[2*q8],   s1a);
      s1b = ffma2(qp[2*q8+1], klo[2*q8+1], s1b);
      s2a = ffma2(qp[2*q8],   kh[2*q8],    s2a);
      s2b = ffma2(qp[2*q8+1], kh[2*q8+1],  s2b);
    }
    float s1s = hsum2(fadd2(s1a, s1b));
    float s2s = hsum2(fadd2(s2a, s2b));

    // scores tiny: softmax w/o max-sub; q pre-scaled so p = 2^s; store
    // UNNORMALIZED p, every lane re-derives the sum from the tile it loads.
    srf[lane] = fex2(s1s);
    if (has2) srf[lane + 32] = fex2(s2s);
    cfence();

    const ulonglong2* s4 = (const ulonglong2*)srf;
    ull aa = 0ull, ab = 0ull, ta = 0ull, tb = 0ull;
    #pragma unroll
    for (int g4 = 0; g4 < 10; g4++) {
      ulonglong2 sv = s4[g4];
      aa = ffma2(sv.x, vp[2*g4],   aa);  ta = fadd2(ta, sv.x);
      ab = ffma2(sv.y, vp[2*g4+1], ab);  tb = fadd2(tb, sv.y);
    }
    float sum = hsum2(fadd2(ta, tb));
    float inv = frcp(sum);
    float acc = hsum2(fadd2(aa, ab));
    float r   = eB[f*DHD + lane];
    eB[f*DHD + lane] = fmaxf(fmaf(acc, inv, r), 0.f);
    cfence();
  }
}

__global__ void __launch_bounds__(448, 1) autoint_kernel(Params p)
{
  extern __shared__ float sm[];
  const int tid  = threadIdx.x;
  const int warp = tid >> 5;
  const int lane = tid & 31;
  const int samp  = blockIdx.x * WARPS + warp;
  const int sampc = (samp < BATCH) ? samp : (BATCH - 1);

  ull*   wbufp = (ull*)sm;                // 1024 ull w1 chunk (8KB)
  float* wp   = sm + WBUF + warp * PW;
  float* eB   = wp;
  float* kT   = wp + KT_OFF;
  float* mA   = wp + MA_OFF;
  float* mB   = wp + MB_OFF;

  // one-time init: kT phys row 7 (= g39) zeros
  for (int i = lane; i < KT_PITCH; i += 32) kT[7*KT_PITCH + i] = 0.f;

  // ---- embedding gather ----
  {
    const int* xr = p.x + sampc * FF;
    for (int i = lane; i < FF * DD; i += 32) {
      int f = i >> 4, d = i & 15;
      int row = xr[f] + f * VOCAB;
      eB[f * DHD + d] = p.emb[row * DD + d];
    }
  }
  cfence();

  attn_layer<16>(wp, p.wq0, p.wk0, p.wv0, p.wr0, lane);
  attn_layer<32>(wp, p.wq1, p.wk1, p.wv1, p.wr1, lane);
  attn_layer<32>(wp, p.wq2, p.wk2, p.wv2, p.wr2, lane);

  __syncthreads();

  // ---- MLP1: 1248 -> 128. 7 groups of 64 threads; group handles 2 samples,
  //      thread covers outputs oo and oo+64. ffma2 over k-pairs. ----
  const int grp = tid >> 6;              // 0..6
  const int oo  = tid & 63;
  const float* hA = sm + WBUF + (2*grp)     * PW;
  const float* hB = sm + WBUF + (2*grp + 1) * PW;
  ull aA0p=0,aA0q=0,aA1p=0,aA1q=0, aB0p=0,aB0q=0,aB1p=0,aB1q=0;
  #pragma unroll 1
  for (int chunk = 0; chunk < 78; chunk++) {
    const int k0 = chunk * 16;
    const float* wsrc = p.w1 + k0 * 128;
    #pragma unroll
    for (int it = 0; it < 3; it++) {
      int idx = tid + 448 * it;
      if (idx < 1024) {
        int pk = idx >> 7, oc = idx & 127;
        wbufp[idx] = pack2(wsrc[(2*pk)*128 + oc], wsrc[(2*pk+1)*128 + oc]);
      }
    }
    __syncthreads();
    #pragma unroll
    for (int pk = 0; pk < 8; pk += 2) {
      ull wA0 = wbufp[pk*128 + oo];
      ull wB0 = wbufp[(pk+1)*128 + oo];
      ull wA1 = wbufp[pk*128 + oo + 64];
      ull wB1 = wbufp[(pk+1)*128 + oo + 64];
      ulonglong2 vA = *(const ulonglong2*)(hA + k0 + 2*pk);
      ulonglong2 vB = *(const ulonglong2*)(hB + k0 + 2*pk);
      aA0p = ffma2(vA.x, wA0, aA0p);  aA0q = ffma2(vA.y, wB0, aA0q);
      aA1p = ffma2(vA.x, wA1, aA1p);  aA1q = ffma2(vA.y, wB1, aA1q);
      aB0p = ffma2(vB.x, wA0, aB0p);  aB0q = ffma2(vB.y, wB0, aB0q);
      aB1p = ffma2(vB.x, wA1, aB1p);  aB1q = ffma2(vB.y, wB1, aB1q);
    }
    __syncthreads();
  }
  {
    float b0 = p.b1[oo], b64 = p.b1[oo + 64];
    float* mAa = sm + WBUF + (2*grp)     * PW + MA_OFF;
    float* mAb = sm + WBUF + (2*grp + 1) * PW + MA_OFF;
    mAa[oo]      = fmaxf(hsum2(fadd2(aA0p, aA0q)) + b0,  0.f);
    mAa[oo + 64] = fmaxf(hsum2(fadd2(aA1p, aA1q)) + b64, 0.f);
    mAb[oo]      = fmaxf(hsum2(fadd2(aB0p, aB0q)) + b0,  0.f);
    mAb[oo + 64] = fmaxf(hsum2(fadd2(aB1p, aB1q)) + b64, 0.f);
  }
  __syncthreads();

  // ---- MLP2: 128 -> 64 (warp-per-sample) ----
  {
    float c0 = p.b2[lane], c1 = p.b2[lane + 32];
    #pragma unroll
    for (int k = 0; k < 128; k += 4) {
      float4 hv = *(const float4*)(mA + k);
      c0 += hv.x*p.w2[(k+0)*64+lane]    + hv.y*p.w2[(k+1)*64+lane]
          + hv.z*p.w2[(k+2)*64+lane]    + hv.w*p.w2[(k+3)*64+lane];
      c1 += hv.x*p.w2[(k+0)*64+lane+32] + hv.y*p.w2[(k+1)*64+lane+32]
          + hv.z*p.w2[(k+2)*64+lane+32] + hv.w*p.w2[(k+3)*64+lane+32];
    }
    mB[lane]      = fmaxf(c0, 0.f);
    mB[lane + 32] = fmaxf(c1, 0.f);
  }
  cfence();

  // ---- MLP3: 64 -> 32 ----
  float d0 = p.b3[lane];
  #pragma unroll
  for (int k = 0; k < 64; k += 4) {
    float4 hv = *(const float4*)(mB + k);
    d0 += hv.x*p.w3[(k+0)*32+lane] + hv.y*p.w3[(k+1)*32+lane]
        + hv.z*p.w3[(k+2)*32+lane] + hv.w*p.w3[(k+3)*32+lane];
  }
  float h3v = fmaxf(d0, 0.f);

  // ---- MLP4: 32 -> 1, sigmoid ----
  float part = h3v * p.w4[lane];
  #pragma unroll
  for (int off = 16; off; off >>= 1) part += __shfl_xor_sync(0xffffffffu, part, off);
  if (lane == 0 && samp < BATCH) {
    float z = part + p.b4[0];
    p.out[samp] = 1.0f / (1.0f + __expf(-z));
  }
}

extern "C" void kernel_launch(void* const* d_in, const int* in_sizes, int n_in,
                              void* d_out, int out_size)
{
  Params p;
  p.x   = (const int*)  d_in[0];
  p.emb = (const float*)d_in[1];
  p.wq0 = (const float*)d_in[2];  p.wk0 = (const float*)d_in[3];
  p.wv0 = (const float*)d_in[4];  p.wr0 = (const float*)d_in[5];
  p.wq1 = (const float*)d_in[6];  p.wk1 = (const float*)d_in[7];
  p.wv1 = (const float*)d_in[8];  p.wr1 = (const float*)d_in[9];
  p.wq2 = (const float*)d_in[10]; p.wk2 = (const float*)d_in[11];
  p.wv2 = (const float*)d_in[12]; p.wr2 = (const float*)d_in[13];
  p.w1  = (const float*)d_in[14]; p.b1  = (const float*)d_in[15];
  p.w2  = (const float*)d_in[16]; p.b2  = (const float*)d_in[17];
  p.w3  = (const float*)d_in[18]; p.b3  = (const float*)d_in[19];
  p.w4  = (const float*)d_in[20]; p.b4  = (const float*)d_in[21];
  p.out = (float*)d_out;

  const int smemBytes = (WBUF + WARPS * PW) * (int)sizeof(float);  // 229,504 B
  cudaFuncSetAttribute(autoint_kernel,
                       cudaFuncAttributeMaxDynamicSharedMemorySize, smemBytes);
  autoint_kernel<<<NCTA, 32 * WARPS, smemBytes>>>(p);
}

// round 9
// speedup vs baseline: 1.0076x; 1.0076x over previous
#include <cuda_runtime.h>
#include <cuda_bf16.h>
#include <math.h>

#define BATCH 16384
#define FF    39
#define DD    16
#define DHD   32
#define VOCAB 10000
#define WARPS 14
#define NCTA  ((BATCH + WARPS - 1) / WARPS)   // 1171

// per-warp shared layout (float indices), all fp32:
//  e:        [0,1248)         e / R / new-e
//  kT hi:    [1248,1520)      phys rows 0..7 = K rows 32..39 (row7=zeros), PERSISTENT
//  transient zone [1520,3856):
//    pass1:  kT phys rows 8..39 (K rows 0..31) at [1520,2608)
//            vstage 32 x 39 at [2608,3856)
//    pass2+: qB fp32 39 x 36 at [1520,2924)   (kT-lo + vstage dead after reg loads)
//  sr0/sr1:  [3856,3936)
//  mA/mB (MLP): [1520,1648)/[1648,1712) over dead qB
#define KT_OFF   1248
#define KT_PITCH 34
#define QB_OFF   1520
#define QB_PITCH 36
#define VS_OFF   2608
#define VS_PITCH 39
#define S_OFF    3856
#define MA_OFF   1520
#define MB_OFF   1648
#define PW       3936
#define WBUF     2048          // CTA w1 chunk: 1024 ull = 16 k-rows x 128 (8KB)

#define LOG2E 1.4426950408889634f

typedef unsigned long long ull;

__device__ __forceinline__ ull ffma2(ull a, ull b, ull c) {
  ull d; asm("fma.rn.f32x2 %0, %1, %2, %3;" : "=l"(d) : "l"(a), "l"(b), "l"(c));
  return d;
}
__device__ __forceinline__ ull fadd2(ull a, ull b) {
  ull d; asm("add.rn.f32x2 %0, %1, %2;" : "=l"(d) : "l"(a), "l"(b));
  return d;
}
__device__ __forceinline__ ull pack2(float lo, float hi) {
  ull v; unsigned int l = __float_as_uint(lo), h = __float_as_uint(hi);
  asm("mov.b64 %0, {%1, %2};" : "=l"(v) : "r"(l), "r"(h));
  return v;
}
__device__ __forceinline__ float hsum2(ull v) {
  unsigned int l, h;
  asm("mov.b64 {%0, %1}, %2;" : "=r"(l), "=r"(h) : "l"(v));
  return __uint_as_float(l) + __uint_as_float(h);
}
__device__ __forceinline__ float frcp(float x) {
  float r; asm("rcp.approx.f32 %0, %1;" : "=f"(r) : "f"(x));
  return r;
}
__device__ __forceinline__ float fex2(float x) {
  float r; asm("ex2.approx.f32 %0, %1;" : "=f"(r) : "f"(x));
  return r;
}
__device__ __forceinline__ void cfence() { asm volatile("" ::: "memory"); }

struct Params {
  const int* x; const float* emb;
  const float* wq0; const float* wk0; const float* wv0; const float* wr0;
  const float* wq1; const float* wk1; const float* wv1; const float* wr1;
  const float* wq2; const float* wk2; const float* wv2; const float* wr2;
  const float* w1; const float* b1; const float* w2; const float* b2;
  const float* w3; const float* b3; const float* w4; const float* b4;
  float* out;
};

template<int DIN>
__device__ __forceinline__ void attn_layer(
    float* wp,
    const float* __restrict__ wq, const float* __restrict__ wk,
    const float* __restrict__ wv, const float* __restrict__ wr, int lane)
{
  float* eB  = wp;
  float* kT  = wp + KT_OFF;
  float* qB  = wp + QB_OFF;
  float* vB2 = wp + VS_OFF;
  float* sr0 = wp + S_OFF;
  float* sr1 = wp + S_OFF + 40;
  constexpr int NP = DIN / 2;

  // ---- Pass 1: K -> kT (row-reordered: phys = g<32 ? g+8 : g-32), V -> vstage ----
  {
    ull wkp[NP], wvp[NP];
    #pragma unroll
    for (int dp = 0; dp < NP; dp++) {
      wkp[dp] = pack2(wk[(2*dp)*DHD + lane], wk[(2*dp+1)*DHD + lane]);
      wvp[dp] = pack2(wv[(2*dp)*DHD + lane], wv[(2*dp+1)*DHD + lane]);
    }
    #pragma unroll 2
    for (int g = 0; g < FF; g++) {
      const ulonglong2* er = (const ulonglong2*)(eB + g*DHD);
      ull ka = 0ull, kb = 0ull, va = 0ull, vb = 0ull;
      #pragma unroll
      for (int q8 = 0; q8 < NP/2; q8++) {
        ulonglong2 ev = er[q8];
        ka = ffma2(ev.x, wkp[2*q8],   ka);  va = ffma2(ev.x, wvp[2*q8],   va);
        kb = ffma2(ev.y, wkp[2*q8+1], kb);  vb = ffma2(ev.y, wvp[2*q8+1], vb);
      }
      int pg = (g < 32) ? (g + 8) : (g - 32);
      kT[pg*KT_PITCH + lane]  = hsum2(fadd2(ka, kb));
      vB2[lane*VS_PITCH + g]  = hsum2(fadd2(va, vb));   // V[g][lane], conflict-free pitch
    }
  }
  cfence();

  // ---- one-time register loads: K rows 0..31 (phys 8..39) and V column ----
  ull klo[16], vp[20];
  {
    #pragma unroll
    for (int dp = 0; dp < 16; dp++)
      klo[dp] = *(const ull*)&kT[(lane + 8)*KT_PITCH + 2*dp];
    const float* vr = vB2 + lane*VS_PITCH;
    #pragma unroll
    for (int gp = 0; gp < 19; gp++)
      vp[gp] = pack2(vr[2*gp], vr[2*gp+1]);
    vp[19] = pack2(vr[38], 0.f);
  }
  cfence();

  // ---- Pass 2: Q (fp32, pre-scaled log2e) -> qB, R -> eB in place ----
  // qB aliases the dead transient kT-lo/vstage zone.
  {
    ull wqp[NP], wrp[NP];
    #pragma unroll
    for (int dp = 0; dp < NP; dp++) {
      wqp[dp] = pack2(wq[(2*dp)*DHD + lane] * LOG2E, wq[(2*dp+1)*DHD + lane] * LOG2E);
      wrp[dp] = pack2(wr[(2*dp)*DHD + lane], wr[(2*dp+1)*DHD + lane]);
    }
    #pragma unroll 2
    for (int g = 0; g < FF; g++) {
      const ulonglong2* er = (const ulonglong2*)(eB + g*DHD);
      ull qa = 0ull, qb = 0ull, ra = 0ull, rb = 0ull;
      #pragma unroll
      for (int q8 = 0; q8 < NP/2; q8++) {
        ulonglong2 ev = er[q8];
        qa = ffma2(ev.x, wqp[2*q8],   qa);  ra = ffma2(ev.x, wrp[2*q8],   ra);
        qb = ffma2(ev.y, wqp[2*q8+1], qb);  rb = ffma2(ev.y, wrp[2*q8+1], rb);
      }
      qB[g*QB_PITCH + lane] = hsum2(fadd2(qa, qb));
      eB[g*DHD + lane]      = hsum2(fadd2(ra, rb));   // R over dead e
    }
  }
  cfence();

  const bool has2  = (lane < 7);
  const int  khrow = has2 ? lane : 7;   // phys 0..6 = K rows 32..38; phys 7 zeros
  const ull* kh = (const ull*)(kT + khrow*KT_PITCH);

  // ---- Phase B: scores, deferred-norm softmax, AV ----
  #pragma unroll 2
  for (int f = 0; f < FF; f++) {
    float* srf = (f & 1) ? sr1 : sr0;
    const ulonglong2* q2 = (const ulonglong2*)(qB + f*QB_PITCH);
    ull s1a = 0ull, s1b = 0ull, s2a = 0ull, s2b = 0ull;
    #pragma unroll
    for (int q8 = 0; q8 < 8; q8++) {
      ulonglong2 qv = q2[q8];
      s1a = ffma2(qv.x, klo[2*q8],   s1a);  s2a = ffma2(qv.x, kh[2*q8],   s2a);
      s1b = ffma2(qv.y, klo[2*q8+1], s1b);  s2b = ffma2(qv.y, kh[2*q8+1], s2b);
    }
    float s1s = hsum2(fadd2(s1a, s1b));
    float s2s = hsum2(fadd2(s2a, s2b));

    // scores tiny: softmax w/o max-sub; Q pre-scaled so p = 2^s. Store
    // UNNORMALIZED p; every lane re-derives the sum from the tile it loads.
    srf[lane] = fex2(s1s);
    if (has2) srf[lane + 32] = fex2(s2s);
    cfence();

    const ulonglong2* s4 = (const ulonglong2*)srf;
    ull aa = 0ull, ab = 0ull, ta = 0ull, tb = 0ull;
    #pragma unroll
    for (int g4 = 0; g4 < 10; g4++) {
      ulonglong2 sv = s4[g4];
      aa = ffma2(sv.x, vp[2*g4],   aa);  ta = fadd2(ta, sv.x);
      ab = ffma2(sv.y, vp[2*g4+1], ab);  tb = fadd2(tb, sv.y);
    }
    float sum = hsum2(fadd2(ta, tb));          // Σ p over all 39 (srf[39]=0)
    float inv = frcp(sum);
    float acc = hsum2(fadd2(aa, ab));
    float r   = eB[f*DHD + lane];
    eB[f*DHD + lane] = fmaxf(fmaf(acc, inv, r), 0.f);
    cfence();
  }
}

__global__ void __launch_bounds__(448, 1) autoint_kernel(Params p)
{
  extern __shared__ float sm[];
  const int tid  = threadIdx.x;
  const int warp = tid >> 5;
  const int lane = tid & 31;
  const int samp  = blockIdx.x * WARPS + warp;
  const int sampc = (samp < BATCH) ? samp : (BATCH - 1);

  ull*   wbufp = (ull*)sm;                // 1024 ull w1 chunk (8KB)
  float* wp   = sm + WBUF + warp * PW;
  float* eB   = wp;
  float* kT   = wp + KT_OFF;
  float* sr   = wp + S_OFF;
  float* mA   = wp + MA_OFF;
  float* mB   = wp + MB_OFF;

  // one-time init: kT phys row 7 (= K row 39) zeros; sr0[39]/sr1[39] zeros.
  // Nothing in the per-layer passes overwrites these.
  for (int i = lane; i < KT_PITCH; i += 32) kT[7*KT_PITCH + i] = 0.f;
  if (lane == 0) { sr[39] = 0.f; sr[40 + 39] = 0.f; }

  // ---- embedding gather ----
  {
    const int* xr = p.x + sampc * FF;
    for (int i = lane; i < FF * DD; i += 32) {
      int f = i >> 4, d = i & 15;
      int row = xr[f] + f * VOCAB;
      eB[f * DHD + d] = p.emb[row * DD + d];
    }
  }
  cfence();

  attn_layer<16>(wp, p.wq0, p.wk0, p.wv0, p.wr0, lane);
  attn_layer<32>(wp, p.wq1, p.wk1, p.wv1, p.wr1, lane);
  attn_layer<32>(wp, p.wq2, p.wk2, p.wv2, p.wr2, lane);

  __syncthreads();

  // ---- MLP1: 1248 -> 128. 7 groups of 64 threads; group handles 2 samples,
  //      thread covers outputs oo and oo+64. ffma2 over k-pairs. ----
  const int grp = tid >> 6;              // 0..6
  const int oo  = tid & 63;
  const float* hA = sm + WBUF + (2*grp)     * PW;
  const float* hB = sm + WBUF + (2*grp + 1) * PW;
  ull aA0p=0,aA0q=0,aA1p=0,aA1q=0, aB0p=0,aB0q=0,aB1p=0,aB1q=0;
  #pragma unroll 1
  for (int chunk = 0; chunk < 78; chunk++) {
    const int k0 = chunk * 16;
    const float* wsrc = p.w1 + k0 * 128;
    #pragma unroll
    for (int it = 0; it < 3; it++) {
      int idx = tid + 448 * it;
      if (idx < 1024) {
        int pk = idx >> 7, oc = idx & 127;
        wbufp[idx] = pack2(wsrc[(2*pk)*128 + oc], wsrc[(2*pk+1)*128 + oc]);
      }
    }
    __syncthreads();
    #pragma unroll
    for (int pk = 0; pk < 8; pk += 2) {
      ull wA0 = wbufp[pk*128 + oo];
      ull wB0 = wbufp[(pk+1)*128 + oo];
      ull wA1 = wbufp[pk*128 + oo + 64];
      ull wB1 = wbufp[(pk+1)*128 + oo + 64];
      ulonglong2 vA = *(const ulonglong2*)(hA + k0 + 2*pk);
      ulonglong2 vB = *(const ulonglong2*)(hB + k0 + 2*pk);
      aA0p = ffma2(vA.x, wA0, aA0p);  aA0q = ffma2(vA.y, wB0, aA0q);
      aA1p = ffma2(vA.x, wA1, aA1p);  aA1q = ffma2(vA.y, wB1, aA1q);
      aB0p = ffma2(vB.x, wA0, aB0p);  aB0q = ffma2(vB.y, wB0, aB0q);
      aB1p = ffma2(vB.x, wA1, aB1p);  aB1q = ffma2(vB.y, wB1, aB1q);
    }
    __syncthreads();
  }
  {
    float b0 = p.b1[oo], b64 = p.b1[oo + 64];
    float* mAa = sm + WBUF + (2*grp)     * PW + MA_OFF;
    float* mAb = sm + WBUF + (2*grp + 1) * PW + MA_OFF;
    mAa[oo]      = fmaxf(hsum2(fadd2(aA0p, aA0q)) + b0,  0.f);
    mAa[oo + 64] = fmaxf(hsum2(fadd2(aA1p, aA1q)) + b64, 0.f);
    mAb[oo]      = fmaxf(hsum2(fadd2(aB0p, aB0q)) + b0,  0.f);
    mAb[oo + 64] = fmaxf(hsum2(fadd2(aB1p, aB1q)) + b64, 0.f);
  }
  __syncthreads();

  // ---- MLP2: 128 -> 64 (warp-per-sample) ----
  {
    float c0 = p.b2[lane], c1 = p.b2[lane + 32];
    #pragma unroll
    for (int k = 0; k < 128; k += 4) {
      float4 hv = *(const float4*)(mA + k);
      c0 += hv.x*p.w2[(k+0)*64+lane]    + hv.y*p.w2[(k+1)*64+lane]
          + hv.z*p.w2[(k+2)*64+lane]    + hv.w*p.w2[(k+3)*64+lane];
      c1 += hv.x*p.w2[(k+0)*64+lane+32] + hv.y*p.w2[(k+1)*64+lane+32]
          + hv.z*p.w2[(k+2)*64+lane+32] + hv.w*p.w2[(k+3)*64+lane+32];
    }
    mB[lane]      = fmaxf(c0, 0.f);
    mB[lane + 32] = fmaxf(c1, 0.f);
  }
  cfence();

  // ---- MLP3: 64 -> 32 ----
  float d0 = p.b3[lane];
  #pragma unroll
  for (int k = 0; k < 64; k += 4) {
    float4 hv = *(const float4*)(mB + k);
    d0 += hv.x*p.w3[(k+0)*32+lane] + hv.y*p.w3[(k+1)*32+lane]
        + hv.z*p.w3[(k+2)*32+lane] + hv.w*p.w3[(k+3)*32+lane];
  }
  float h3v = fmaxf(d0, 0.f);

  // ---- MLP4: 32 -> 1, sigmoid ----
  float part = h3v * p.w4[lane];
  #pragma unroll
  for (int off = 16; off; off >>= 1) part += __shfl_xor_sync(0xffffffffu, part, off);
  if (lane == 0 && samp < BATCH) {
    float z = part + p.b4[0];
    p.out[samp] = 1.0f / (1.0f + __expf(-z));
  }
}

extern "C" void kernel_launch(void* const* d_in, const int* in_sizes, int n_in,
                              void* d_out, int out_size)
{
  Params p;
  p.x   = (const int*)  d_in[0];
  p.emb = (const float*)d_in[1];
  p.wq0 = (const float*)d_in[2];  p.wk0 = (const float*)d_in[3];
  p.wv0 = (const float*)d_in[4];  p.wr0 = (const float*)d_in[5];
  p.wq1 = (const float*)d_in[6];  p.wk1 = (const float*)d_in[7];
  p.wv1 = (const float*)d_in[8];  p.wr1 = (const float*)d_in[9];
  p.wq2 = (const float*)d_in[10]; p.wk2 = (const float*)d_in[11];
  p.wv2 = (const float*)d_in[12]; p.wr2 = (const float*)d_in[13];
  p.w1  = (const float*)d_in[14]; p.b1  = (const float*)d_in[15];
  p.w2  = (const float*)d_in[16]; p.b2  = (const float*)d_in[17];
  p.w3  = (const float*)d_in[18]; p.b3  = (const float*)d_in[19];
  p.w4  = (const float*)d_in[20]; p.b4  = (const float*)d_in[21];
  p.out = (float*)d_out;

  const int smemBytes = (WBUF + WARPS * PW) * (int)sizeof(float);  // 228,608 B
  cudaFuncSetAttribute(autoint_kernel,
                       cudaFuncAttributeMaxDynamicSharedMemorySize, smemBytes);
  autoint_kernel<<<NCTA, 32 * WARPS, smemBytes>>>(p);
}

// round 10
// speedup vs baseline: 1.1807x; 1.1717x over previous
#include <cuda_runtime.h>
#include <cuda_bf16.h>
#include <math.h>

#define BATCH 16384
#define FF    39
#define DD    16
#define DHD   32
#define VOCAB 10000
#define WARPS 12
#define NCTA  ((BATCH + WARPS - 1) / WARPS)   // 1366

// per-warp shared layout (floats)
#define E_OFF   0              // e / R / new-e : 39*32 = 1248
#define KT_OFF  1248           // K rows: 40 x pitch 34 = 1360 (row 39 = zeros)
#define KT_PITCH 34
#define QB_OFF  2608           // Q rows: 39 x pitch 36 ; aliased by V staging (32 x 42)
#define QB_PITCH 36
#define VB_PITCH 42
#define PW      4096
#define MA_OFF  1248           // MLP hidden 128 (over dead kT)
#define MB_OFF  1376           // MLP hidden 64
#define WBUF    4096           // CTA-shared w1 chunk: 2048 ull (16KB)

#define LOG2E 1.4426950408889634f

typedef unsigned long long ull;

__device__ __forceinline__ ull ffma2(ull a, ull b, ull c) {
  ull d; asm("fma.rn.f32x2 %0, %1, %2, %3;" : "=l"(d) : "l"(a), "l"(b), "l"(c));
  return d;
}
__device__ __forceinline__ ull fadd2(ull a, ull b) {
  ull d; asm("add.rn.f32x2 %0, %1, %2;" : "=l"(d) : "l"(a), "l"(b));
  return d;
}
__device__ __forceinline__ ull pack2(float lo, float hi) {
  ull v; unsigned int l = __float_as_uint(lo), h = __float_as_uint(hi);
  asm("mov.b64 %0, {%1, %2};" : "=l"(v) : "r"(l), "r"(h));
  return v;
}
__device__ __forceinline__ float hsum2(ull v) {
  unsigned int l, h;
  asm("mov.b64 {%0, %1}, %2;" : "=r"(l), "=r"(h) : "l"(v));
  return __uint_as_float(l) + __uint_as_float(h);
}
__device__ __forceinline__ float frcp(float x) {
  float r; asm("rcp.approx.f32 %0, %1;" : "=f"(r) : "f"(x));
  return r;
}
__device__ __forceinline__ float fex2(float x) {
  float r; asm("ex2.approx.f32 %0, %1;" : "=f"(r) : "f"(x));
  return r;
}
__device__ __forceinline__ void cfence() { asm volatile("" ::: "memory"); }

struct Params {
  const int* x; const float* emb;
  const float* wq0; const float* wk0; const float* wv0; const float* wr0;
  const float* wq1; const float* wk1; const float* wv1; const float* wr1;
  const float* wq2; const float* wk2; const float* wv2; const float* wr2;
  const float* w1; const float* b1; const float* w2; const float* b2;
  const float* w3; const float* b3; const float* w4; const float* b4;
  float* out;
};

template<int DIN>
__device__ __forceinline__ void attn_layer(
    float* wp,
    const float* __restrict__ wq, const float* __restrict__ wk,
    const float* __restrict__ wv, const float* __restrict__ wr, int lane)
{
  float* eB  = wp + E_OFF;
  float* kT  = wp + KT_OFF;
  float* qB  = wp + QB_OFF;    // also V staging
  constexpr int NP = DIN / 2;

  // ---- Pass 1: K -> kT smem (transposed), V -> staging ----
  {
    ull wkp[NP], wvp[NP];
    #pragma unroll
    for (int dp = 0; dp < NP; dp++) {
      wkp[dp] = pack2(wk[(2*dp)*DHD + lane], wk[(2*dp+1)*DHD + lane]);
      wvp[dp] = pack2(wv[(2*dp)*DHD + lane], wv[(2*dp+1)*DHD + lane]);
    }
    #pragma unroll 2
    for (int g = 0; g < FF; g++) {
      const ulonglong2* er = (const ulonglong2*)(eB + g*DHD);
      ull ka = 0ull, kb = 0ull, va = 0ull, vb = 0ull;
      #pragma unroll
      for (int q8 = 0; q8 < NP/2; q8++) {
        ulonglong2 ev = er[q8];
        ka = ffma2(ev.x, wkp[2*q8],   ka);  va = ffma2(ev.x, wvp[2*q8],   va);
        kb = ffma2(ev.y, wkp[2*q8+1], kb);  vb = ffma2(ev.y, wvp[2*q8+1], vb);
      }
      kT[g*KT_PITCH + lane]  = hsum2(fadd2(ka, kb));
      qB[lane*VB_PITCH + g]  = hsum2(fadd2(va, vb));   // V[g][lane] staged transposed
    }
    qB[lane*VB_PITCH + 39] = 0.f;
  }
  cfence();

  // ---- one-time register loads: K rows (lane, lane+32) and V column ----
  ull klo[16], khi[16], vp[20];
  {
    const int hrow = (lane < 7) ? (lane + 32) : 39;   // row 39 is zeros
    #pragma unroll
    for (int dp = 0; dp < 16; dp++) {
      klo[dp] = *(const ull*)&kT[lane*KT_PITCH + 2*dp];
      khi[dp] = *(const ull*)&kT[hrow*KT_PITCH + 2*dp];
    }
    #pragma unroll
    for (int gp = 0; gp < 20; gp++)
      vp[gp] = *(const ull*)&qB[lane*VB_PITCH + 2*gp];   // pair (38,39): hi = 0
  }
  cfence();

  // ---- Pass 2: Q (pre-scaled by log2e) -> qB, R -> eB (in place) ----
  {
    ull wqp[NP], wrp[NP];
    #pragma unroll
    for (int dp = 0; dp < NP; dp++) {
      wqp[dp] = pack2(wq[(2*dp)*DHD + lane] * LOG2E, wq[(2*dp+1)*DHD + lane] * LOG2E);
      wrp[dp] = pack2(wr[(2*dp)*DHD + lane], wr[(2*dp+1)*DHD + lane]);
    }
    #pragma unroll 2
    for (int g = 0; g < FF; g++) {
      const ulonglong2* er = (const ulonglong2*)(eB + g*DHD);
      ull qa = 0ull, qb = 0ull, ra = 0ull, rb = 0ull;
      #pragma unroll
      for (int q8 = 0; q8 < NP/2; q8++) {
        ulonglong2 ev = er[q8];
        qa = ffma2(ev.x, wqp[2*q8],   qa);  ra = ffma2(ev.x, wrp[2*q8],   ra);
        qb = ffma2(ev.y, wqp[2*q8+1], qb);  rb = ffma2(ev.y, wrp[2*q8+1], rb);
      }
      qB[g*QB_PITCH + lane] = hsum2(fadd2(qa, qb));
      eB[g*DHD + lane]      = hsum2(fadd2(ra, rb));   // R over dead e
    }
  }
  cfence();

  // ---- Phase B: scores, deferred-norm softmax, AV with SHFL p-exchange ----
  // No smem stores in the loop except the per-lane eB row write; p values are
  // distributed via idx-shuffles -> no store->load smem chain, so consecutive
  // f-rows pipeline freely.
  #pragma unroll 2
  for (int f = 0; f < FF; f++) {
    const ulonglong2* q2 = (const ulonglong2*)(qB + f*QB_PITCH);
    ull s1a = 0ull, s1b = 0ull, s2a = 0ull, s2b = 0ull;
    #pragma unroll
    for (int q8 = 0; q8 < 8; q8++) {
      ulonglong2 qv = q2[q8];
      s1a = ffma2(qv.x, klo[2*q8],   s1a);  s2a = ffma2(qv.x, khi[2*q8],   s2a);
      s1b = ffma2(qv.y, klo[2*q8+1], s1b);  s2b = ffma2(qv.y, khi[2*q8+1], s2b);
    }
    // scores tiny (inputs ~N(0,0.05)): softmax w/o max-sub; Q pre-scaled, p = 2^s
    float p1 = fex2(hsum2(fadd2(s1a, s1b)));   // p for g = lane
    float p2 = fex2(hsum2(fadd2(s2a, s2b)));   // p for g = lane+32 (lanes 0..6; else 2^0, unused)

    ull aa = 0ull, ab = 0ull, ta = 0ull, tb = 0ull;
    #pragma unroll
    for (int j = 0; j < 16; j += 2) {
      ull pj0 = pack2(__shfl_sync(0xffffffffu, p1, 2*j),
                      __shfl_sync(0xffffffffu, p1, 2*j + 1));
      ull pj1 = pack2(__shfl_sync(0xffffffffu, p1, 2*j + 2),
                      __shfl_sync(0xffffffffu, p1, 2*j + 3));
      aa = ffma2(pj0, vp[j],   aa);  ta = fadd2(ta, pj0);
      ab = ffma2(pj1, vp[j+1], ab);  tb = fadd2(tb, pj1);
    }
    {
      ull p16 = pack2(__shfl_sync(0xffffffffu, p2, 0), __shfl_sync(0xffffffffu, p2, 1));
      ull p17 = pack2(__shfl_sync(0xffffffffu, p2, 2), __shfl_sync(0xffffffffu, p2, 3));
      ull p18 = pack2(__shfl_sync(0xffffffffu, p2, 4), __shfl_sync(0xffffffffu, p2, 5));
      ull p19 = pack2(__shfl_sync(0xffffffffu, p2, 6), 0.f);
      aa = ffma2(p16, vp[16], aa);  ta = fadd2(ta, p16);
      ab = ffma2(p17, vp[17], ab);  tb = fadd2(tb, p17);
      aa = ffma2(p18, vp[18], aa);  ta = fadd2(ta, p18);
      ab = ffma2(p19, vp[19], ab);  tb = fadd2(tb, p19);   // vp[19] hi is V[39]=0 anyway
    }
    float sum = hsum2(fadd2(ta, tb));          // Σ p over all 39
    float inv = frcp(sum);
    float acc = hsum2(fadd2(aa, ab));
    float r   = eB[f*DHD + lane];              // R (stored in pass 2, same lane)
    eB[f*DHD + lane] = fmaxf(fmaf(acc, inv, r), 0.f);
  }
  cfence();
}

__global__ void __launch_bounds__(384, 1) autoint_kernel(Params p)
{
  extern __shared__ float sm[];
  const int tid  = threadIdx.x;
  const int warp = tid >> 5;
  const int lane = tid & 31;
  const int samp  = blockIdx.x * WARPS + warp;
  const int sampc = (samp < BATCH) ? samp : (BATCH - 1);

  ull*   wbufp = (ull*)sm;                // [16][128] k-paired w1 chunk (16KB)
  float* wp   = sm + WBUF + warp * PW;    // per-warp region
  float* eB   = wp + E_OFF;
  float* kT   = wp + KT_OFF;
  float* mA   = wp + MA_OFF;
  float* mB   = wp + MB_OFF;

  // one-time init: kT row 39 zeros
  for (int i = lane; i < KT_PITCH; i += 32) kT[39*KT_PITCH + i] = 0.f;

  // ---- embedding gather ----
  {
    const int* xr = p.x + sampc * FF;
    for (int i = lane; i < FF * DD; i += 32) {
      int f = i >> 4, d = i & 15;
      int row = xr[f] + f * VOCAB;
      eB[f * DHD + d] = p.emb[row * DD + d];
    }
  }
  cfence();

  attn_layer<16>(wp, p.wq0, p.wk0, p.wv0, p.wr0, lane);
  attn_layer<32>(wp, p.wq1, p.wk1, p.wv1, p.wr1, lane);
  attn_layer<32>(wp, p.wq2, p.wk2, p.wv2, p.wr2, lane);

  __syncthreads();

  // ---- MLP1: 1248 -> 128, output-stationary, packed ffma2 over k-pairs ----
  const int o  = tid & 127;
  const int sg = tid >> 7;                // 0..2 -> samples sg*4 .. sg*4+3
  const float* h0 = sm + WBUF + (sg*4 + 0) * PW;
  const float* h1 = sm + WBUF + (sg*4 + 1) * PW;
  const float* h2 = sm + WBUF + (sg*4 + 2) * PW;
  const float* h3 = sm + WBUF + (sg*4 + 3) * PW;
  ull a0p = 0ull, a0q = 0ull, a1p = 0ull, a1q = 0ull;
  ull a2p = 0ull, a2q = 0ull, a3p = 0ull, a3q = 0ull;
  #pragma unroll 1
  for (int chunk = 0; chunk < 39; chunk++) {
    const int k0 = chunk * 32;
    const float* wsrc = p.w1 + k0 * 128;
    // repack chunk: wbufp[pk*128+o] = (w1[k0+2pk][o], w1[k0+2pk+1][o])
    #pragma unroll
    for (int it = 0; it < 6; it++) {
      int idx = tid + 384 * it;
      if (idx < 2048) {
        int pk = idx >> 7, oc = idx & 127;
        wbufp[idx] = pack2(wsrc[(2*pk)*128 + oc], wsrc[(2*pk+1)*128 + oc]);
      }
    }
    __syncthreads();
    #pragma unroll
    for (int pk = 0; pk < 16; pk += 2) {
      ull wA = wbufp[pk*128 + o];
      ull wB = wbufp[(pk+1)*128 + o];
      ulonglong2 v0 = *(const ulonglong2*)(h0 + k0 + 2*pk);
      ulonglong2 v1 = *(const ulonglong2*)(h1 + k0 + 2*pk);
      ulonglong2 v2 = *(const ulonglong2*)(h2 + k0 + 2*pk);
      ulonglong2 v3 = *(const ulonglong2*)(h3 + k0 + 2*pk);
      a0p = ffma2(v0.x, wA, a0p);  a0q = ffma2(v0.y, wB, a0q);
      a1p = ffma2(v1.x, wA, a1p);  a1q = ffma2(v1.y, wB, a1q);
      a2p = ffma2(v2.x, wA, a2p);  a2q = ffma2(v2.y, wB, a2q);
      a3p = ffma2(v3.x, wA, a3p);  a3q = ffma2(v3.y, wB, a3q);
    }
    __syncthreads();
  }
  {
    float bb = p.b1[o];
    (sm + WBUF + (sg*4 + 0)*PW + MA_OFF)[o] = fmaxf(hsum2(fadd2(a0p, a0q)) + bb, 0.f);
    (sm + WBUF + (sg*4 + 1)*PW + MA_OFF)[o] = fmaxf(hsum2(fadd2(a1p, a1q)) + bb, 0.f);
    (sm + WBUF + (sg*4 + 2)*PW + MA_OFF)[o] = fmaxf(hsum2(fadd2(a2p, a2q)) + bb, 0.f);
    (sm + WBUF + (sg*4 + 3)*PW + MA_OFF)[o] = fmaxf(hsum2(fadd2(a3p, a3q)) + bb, 0.f);
  }
  __syncthreads();

  // ---- MLP2: 128 -> 64 (warp-per-sample) ----
  {
    float c0 = p.b2[lane], c1 = p.b2[lane + 32];
    #pragma unroll
    for (int k = 0; k < 128; k += 4) {
      float4 hv = *(const float4*)(mA + k);
      c0 += hv.x*p.w2[(k+0)*64+lane]    + hv.y*p.w2[(k+1)*64+lane]
          + hv.z*p.w2[(k+2)*64+lane]    + hv.w*p.w2[(k+3)*64+lane];
      c1 += hv.x*p.w2[(k+0)*64+lane+32] + hv.y*p.w2[(k+1)*64+lane+32]
          + hv.z*p.w2[(k+2)*64+lane+32] + hv.w*p.w2[(k+3)*64+lane+32];
    }
    mB[lane]      = fmaxf(c0, 0.f);
    mB[lane + 32] = fmaxf(c1, 0.f);
  }
  cfence();

  // ---- MLP3: 64 -> 32 ----
  float d0 = p.b3[lane];
  #pragma unroll
  for (int k = 0; k < 64; k += 4) {
    float4 hv = *(const float4*)(mB + k);
    d0 += hv.x*p.w3[(k+0)*32+lane] + hv.y*p.w3[(k+1)*32+lane]
        + hv.z*p.w3[(k+2)*32+lane] + hv.w*p.w3[(k+3)*32+lane];
  }
  float h3v = fmaxf(d0, 0.f);

  // ---- MLP4: 32 -> 1, sigmoid ----
  float part = h3v * p.w4[lane];
  #pragma unroll
  for (int off = 16; off; off >>= 1) part += __shfl_xor_sync(0xffffffffu, part, off);
  if (lane == 0 && samp < BATCH) {
    float z = part + p.b4[0];
    p.out[samp] = 1.0f / (1.0f + __expf(-z));
  }
}

extern "C" void kernel_launch(void* const* d_in, const int* in_sizes, int n_in,
                              void* d_out, int out_size)
{
  Params p;
  p.x   = (const int*)  d_in[0];
  p.emb = (const float*)d_in[1];
  p.wq0 = (const float*)d_in[2];  p.wk0 = (const float*)d_in[3];
  p.wv0 = (const float*)d_in[4];  p.wr0 = (const float*)d_in[5];
  p.wq1 = (const float*)d_in[6];  p.wk1 = (const float*)d_in[7];
  p.wv1 = (const float*)d_in[8];  p.wr1 = (const float*)d_in[9];
  p.wq2 = (const float*)d_in[10]; p.wk2 = (const float*)d_in[11];
  p.wv2 = (const float*)d_in[12]; p.wr2 = (const float*)d_in[13];
  p.w1  = (const float*)d_in[14]; p.b1  = (const float*)d_in[15];
  p.w2  = (const float*)d_in[16]; p.b2  = (const float*)d_in[17];
  p.w3  = (const float*)d_in[18]; p.b3  = (const float*)d_in[19];
  p.w4  = (const float*)d_in[20]; p.b4  = (const float*)d_in[21];
  p.out = (float*)d_out;

  const int smemBytes = (WBUF + WARPS * PW) * (int)sizeof(float);
  cudaFuncSetAttribute(autoint_kernel,
                       cudaFuncAttributeMaxDynamicSharedMemorySize, smemBytes);
  autoint_kernel<<<NCTA, 32 * WARPS, smemBytes>>>(p);
}